// round 4
// baseline (speedup 1.0000x reference)
#include <cuda_runtime.h>

// DiffJPEG: per 8x8 block  Y = D X D^T ; Yq = round(Y/Q)*Q ; Z = D^T Yq D
// img: (32, 3, 512, 512) fp32 -> same shape fp32.
// One thread per 8x8 block, all in registers. 8-pt DCT via even/odd
// butterfly (40 ops vs 64 FMA), coefficients as compile-time immediates.
// Streaming (.cs) loads/stores; round-half-even via 1.5*2^23 magic adds.

namespace {

constexpr float A_  = 0.35355339059327373f;  // sqrt(1/8)
constexpr float B1_ = 0.49039264020161522f;
constexpr float B2_ = 0.46193976625564337f;
constexpr float B3_ = 0.41573480615127262f;
constexpr float B4_ = 0.35355339059327379f;
constexpr float B5_ = 0.27778511650980114f;
constexpr float B6_ = 0.19134171618254492f;
constexpr float B7_ = 0.09754516100806417f;

constexpr float RND_MAGIC = 12582912.0f;  // 1.5 * 2^23

// quality=50 -> scale=100 -> Q = floor(q + 0.5) = q_luma exactly.
__device__ constexpr float Qm[8][8] = {
    { 16.f, 11.f, 10.f, 16.f,  24.f,  40.f,  51.f,  61.f},
    { 12.f, 12.f, 14.f, 19.f,  26.f,  58.f,  60.f,  55.f},
    { 14.f, 13.f, 16.f, 24.f,  40.f,  57.f,  69.f,  56.f},
    { 14.f, 17.f, 22.f, 29.f,  51.f,  87.f,  80.f,  62.f},
    { 18.f, 22.f, 37.f, 56.f,  68.f, 109.f, 103.f,  77.f},
    { 24.f, 35.f, 55.f, 64.f,  81.f, 104.f, 113.f,  92.f},
    { 49.f, 64.f, 78.f, 87.f, 103.f, 121.f, 120.f, 101.f},
    { 72.f, 92.f, 95.f, 98.f, 112.f, 100.f, 103.f,  99.f},
};

// Exact round-half-to-even for |x| < 2^22 (== rintf == jnp.round here).
// __fadd_rn blocks any compiler re-association of the two adds.
__device__ __forceinline__ float round_even(float x) {
    return __fadd_rn(__fadd_rn(x, RND_MAGIC), -RND_MAGIC);
}

// Forward 8-pt DCT (y = D x), even/odd butterfly.
__device__ __forceinline__ void fwd8(
    float x0, float x1, float x2, float x3,
    float x4, float x5, float x6, float x7,
    float& y0, float& y1, float& y2, float& y3,
    float& y4, float& y5, float& y6, float& y7)
{
    const float s0 = x0 + x7, s1 = x1 + x6, s2 = x2 + x5, s3 = x3 + x4;
    const float d0 = x0 - x7, d1 = x1 - x6, d2 = x2 - x5, d3 = x3 - x4;

    y0 = A_ * ((s0 + s3) + (s1 + s2));
    y4 = B4_ * ((s0 + s3) - (s1 + s2));
    y2 = fmaf(B2_, s0, fmaf(B6_, s1, fmaf(-B6_, s2, -B2_ * s3)));
    y6 = fmaf(B6_, s0, fmaf(-B2_, s1, fmaf(B2_, s2, -B6_ * s3)));

    y1 = fmaf(B1_, d0, fmaf(B3_, d1, fmaf(B5_, d2,  B7_ * d3)));
    y3 = fmaf(B3_, d0, fmaf(-B7_, d1, fmaf(-B1_, d2, -B5_ * d3)));
    y5 = fmaf(B5_, d0, fmaf(-B1_, d1, fmaf(B7_, d2,  B3_ * d3)));
    y7 = fmaf(B7_, d0, fmaf(-B5_, d1, fmaf(B3_, d2, -B1_ * d3)));
}

// Inverse 8-pt DCT (x = D^T c), even/odd recombination.
__device__ __forceinline__ void inv8(
    float c0, float c1, float c2, float c3,
    float c4, float c5, float c6, float c7,
    float& x0, float& x1, float& x2, float& x3,
    float& x4, float& x5, float& x6, float& x7)
{
    const float a0 = fmaf(A_, c0,  B4_ * c4);
    const float a1 = fmaf(A_, c0, -B4_ * c4);
    const float e0 = fmaf(B2_, c2,  fmaf(B6_, c6, a0));
    const float e1 = fmaf(B6_, c2, fmaf(-B2_, c6, a1));
    const float e2 = fmaf(-B6_, c2, fmaf(B2_, c6, a1));
    const float e3 = fmaf(-B2_, c2, fmaf(-B6_, c6, a0));

    const float o0 = fmaf(B1_, c1, fmaf(B3_, c3, fmaf(B5_, c5,  B7_ * c7)));
    const float o1 = fmaf(B3_, c1, fmaf(-B7_, c3, fmaf(-B1_, c5, -B5_ * c7)));
    const float o2 = fmaf(B5_, c1, fmaf(-B1_, c3, fmaf(B7_, c5,  B3_ * c7)));
    const float o3 = fmaf(B7_, c1, fmaf(-B5_, c3, fmaf(B3_, c5, -B1_ * c7)));

    x0 = e0 + o0;  x7 = e0 - o0;
    x1 = e1 + o1;  x6 = e1 - o1;
    x2 = e2 + o2;  x5 = e2 - o2;
    x3 = e3 + o3;  x4 = e3 - o3;
}

}  // namespace

// 32*3 images of 512x512, 64x64 blocks each
static constexpr int NUM_BLOCKS_TOTAL = 32 * 3 * 64 * 64;  // 393216
static constexpr int THREADS_PER_CTA  = 256;

__global__ void __launch_bounds__(THREADS_PER_CTA)
diffjpeg_kernel(const float* __restrict__ in, float* __restrict__ out) {
    const int tid = blockIdx.x * THREADS_PER_CTA + threadIdx.x;
    const int bx = tid & 63;          // block col (0..63)
    const int by = (tid >> 6) & 63;   // block row (0..63)
    const int bc = tid >> 12;         // image-plane (0..95)

    const size_t base = ((size_t)bc << 18) + ((size_t)(by << 3) << 9) + ((size_t)bx << 3);
    const float* __restrict__ p = in + base;
    float* __restrict__ q = out + base;

    float x[8][8];

    // ---- load 8x8 block (2x LDG.128.CS per row; warp covers contiguous 1KB) ----
#pragma unroll
    for (int r = 0; r < 8; r++) {
        const float4 v0 = __ldcs(reinterpret_cast<const float4*>(p + ((size_t)r << 9)));
        const float4 v1 = __ldcs(reinterpret_cast<const float4*>(p + ((size_t)r << 9) + 4));
        x[r][0] = v0.x; x[r][1] = v0.y; x[r][2] = v0.z; x[r][3] = v0.w;
        x[r][4] = v1.x; x[r][5] = v1.y; x[r][6] = v1.z; x[r][7] = v1.w;
    }

    // ---- forward DCT: rows (X D^T), then cols ----
#pragma unroll
    for (int i = 0; i < 8; i++) {
        fwd8(x[i][0], x[i][1], x[i][2], x[i][3], x[i][4], x[i][5], x[i][6], x[i][7],
             x[i][0], x[i][1], x[i][2], x[i][3], x[i][4], x[i][5], x[i][6], x[i][7]);
    }
#pragma unroll
    for (int j = 0; j < 8; j++) {
        fwd8(x[0][j], x[1][j], x[2][j], x[3][j], x[4][j], x[5][j], x[6][j], x[7][j],
             x[0][j], x[1][j], x[2][j], x[3][j], x[4][j], x[5][j], x[6][j], x[7][j]);
    }

    // ---- quantize (round half-to-even) + dequantize ----
#pragma unroll
    for (int i = 0; i < 8; i++) {
#pragma unroll
        for (int j = 0; j < 8; j++) {
            x[i][j] = round_even(x[i][j] * (1.0f / Qm[i][j])) * Qm[i][j];
        }
    }

    // ---- inverse DCT: rows, then cols ----
#pragma unroll
    for (int i = 0; i < 8; i++) {
        inv8(x[i][0], x[i][1], x[i][2], x[i][3], x[i][4], x[i][5], x[i][6], x[i][7],
             x[i][0], x[i][1], x[i][2], x[i][3], x[i][4], x[i][5], x[i][6], x[i][7]);
    }
#pragma unroll
    for (int j = 0; j < 8; j++) {
        inv8(x[0][j], x[1][j], x[2][j], x[3][j], x[4][j], x[5][j], x[6][j], x[7][j],
             x[0][j], x[1][j], x[2][j], x[3][j], x[4][j], x[5][j], x[6][j], x[7][j]);
    }

    // ---- store 8x8 block (STG.128.CS) ----
#pragma unroll
    for (int r = 0; r < 8; r++) {
        float4 v0, v1;
        v0.x = x[r][0]; v0.y = x[r][1]; v0.z = x[r][2]; v0.w = x[r][3];
        v1.x = x[r][4]; v1.y = x[r][5]; v1.z = x[r][6]; v1.w = x[r][7];
        __stcs(reinterpret_cast<float4*>(q + ((size_t)r << 9)),     v0);
        __stcs(reinterpret_cast<float4*>(q + ((size_t)r << 9) + 4), v1);
    }
}

extern "C" void kernel_launch(void* const* d_in, const int* in_sizes, int n_in,
                              void* d_out, int out_size) {
    (void)in_sizes; (void)n_in; (void)out_size;
    const float* img = (const float*)d_in[0];
    float* out = (float*)d_out;
    const int grid = NUM_BLOCKS_TOTAL / THREADS_PER_CTA;  // 1536
    diffjpeg_kernel<<<grid, THREADS_PER_CTA>>>(img, out);
}

// round 13
// speedup vs baseline: 1.1464x; 1.1464x over previous
#include <cuda_runtime.h>

// DiffJPEG: per 8x8 block  Y = D X D^T ; Yq = round(Y/Q)*Q ; Z = D^T Yq D
// img: (32, 3, 512, 512) fp32 -> same shape fp32.
// One thread per 8x8 block, all in registers. 8-pt DCT via even/odd
// butterfly, coefficients as compile-time immediates. Streaming (.cs) I/O.
// __launch_bounds__(256,3) caps regs at 85 -> 3 CTAs/SM (24 warps) for
// latency hiding (R4 profile: occ 20.3%, issue 45%, DRAM 47% -> latency-bound).

namespace {

constexpr float A_  = 0.35355339059327373f;  // sqrt(1/8)
constexpr float B1_ = 0.49039264020161522f;
constexpr float B2_ = 0.46193976625564337f;
constexpr float B3_ = 0.41573480615127262f;
constexpr float B4_ = 0.35355339059327379f;
constexpr float B5_ = 0.27778511650980114f;
constexpr float B6_ = 0.19134171618254492f;
constexpr float B7_ = 0.09754516100806417f;

constexpr float RND_MAGIC = 12582912.0f;  // 1.5 * 2^23

// quality=50 -> scale=100 -> Q = floor(q + 0.5) = q_luma exactly.
__device__ constexpr float Qm[8][8] = {
    { 16.f, 11.f, 10.f, 16.f,  24.f,  40.f,  51.f,  61.f},
    { 12.f, 12.f, 14.f, 19.f,  26.f,  58.f,  60.f,  55.f},
    { 14.f, 13.f, 16.f, 24.f,  40.f,  57.f,  69.f,  56.f},
    { 14.f, 17.f, 22.f, 29.f,  51.f,  87.f,  80.f,  62.f},
    { 18.f, 22.f, 37.f, 56.f,  68.f, 109.f, 103.f,  77.f},
    { 24.f, 35.f, 55.f, 64.f,  81.f, 104.f, 113.f,  92.f},
    { 49.f, 64.f, 78.f, 87.f, 103.f, 121.f, 120.f, 101.f},
    { 72.f, 92.f, 95.f, 98.f, 112.f, 100.f, 103.f,  99.f},
};

// Exact round-half-to-even for |x| < 2^22 (== rintf == jnp.round here).
// __fadd_rn blocks compiler re-association of the two adds.
__device__ __forceinline__ float round_even(float x) {
    return __fadd_rn(__fadd_rn(x, RND_MAGIC), -RND_MAGIC);
}

// Forward 8-pt DCT (y = D x), even/odd butterfly.
__device__ __forceinline__ void fwd8(
    float x0, float x1, float x2, float x3,
    float x4, float x5, float x6, float x7,
    float& y0, float& y1, float& y2, float& y3,
    float& y4, float& y5, float& y6, float& y7)
{
    const float s0 = x0 + x7, s1 = x1 + x6, s2 = x2 + x5, s3 = x3 + x4;
    const float d0 = x0 - x7, d1 = x1 - x6, d2 = x2 - x5, d3 = x3 - x4;

    y0 = A_ * ((s0 + s3) + (s1 + s2));
    y4 = B4_ * ((s0 + s3) - (s1 + s2));
    y2 = fmaf(B2_, s0, fmaf(B6_, s1, fmaf(-B6_, s2, -B2_ * s3)));
    y6 = fmaf(B6_, s0, fmaf(-B2_, s1, fmaf(B2_, s2, -B6_ * s3)));

    y1 = fmaf(B1_, d0, fmaf(B3_, d1, fmaf(B5_, d2,  B7_ * d3)));
    y3 = fmaf(B3_, d0, fmaf(-B7_, d1, fmaf(-B1_, d2, -B5_ * d3)));
    y5 = fmaf(B5_, d0, fmaf(-B1_, d1, fmaf(B7_, d2,  B3_ * d3)));
    y7 = fmaf(B7_, d0, fmaf(-B5_, d1, fmaf(B3_, d2, -B1_ * d3)));
}

// Inverse 8-pt DCT (x = D^T c), even/odd recombination.
__device__ __forceinline__ void inv8(
    float c0, float c1, float c2, float c3,
    float c4, float c5, float c6, float c7,
    float& x0, float& x1, float& x2, float& x3,
    float& x4, float& x5, float& x6, float& x7)
{
    const float a0 = fmaf(A_, c0,  B4_ * c4);
    const float a1 = fmaf(A_, c0, -B4_ * c4);
    const float e0 = fmaf(B2_, c2,  fmaf(B6_, c6, a0));
    const float e1 = fmaf(B6_, c2, fmaf(-B2_, c6, a1));
    const float e2 = fmaf(-B6_, c2, fmaf(B2_, c6, a1));
    const float e3 = fmaf(-B2_, c2, fmaf(-B6_, c6, a0));

    const float o0 = fmaf(B1_, c1, fmaf(B3_, c3, fmaf(B5_, c5,  B7_ * c7)));
    const float o1 = fmaf(B3_, c1, fmaf(-B7_, c3, fmaf(-B1_, c5, -B5_ * c7)));
    const float o2 = fmaf(B5_, c1, fmaf(-B1_, c3, fmaf(B7_, c5,  B3_ * c7)));
    const float o3 = fmaf(B7_, c1, fmaf(-B5_, c3, fmaf(B3_, c5, -B1_ * c7)));

    x0 = e0 + o0;  x7 = e0 - o0;
    x1 = e1 + o1;  x6 = e1 - o1;
    x2 = e2 + o2;  x5 = e2 - o2;
    x3 = e3 + o3;  x4 = e3 - o3;
}

}  // namespace

// 32*3 images of 512x512, 64x64 blocks each
static constexpr int NUM_BLOCKS_TOTAL = 32 * 3 * 64 * 64;  // 393216
static constexpr int THREADS_PER_CTA  = 256;

__global__ void __launch_bounds__(THREADS_PER_CTA, 3)
diffjpeg_kernel(const float* __restrict__ in, float* __restrict__ out) {
    const int tid = blockIdx.x * THREADS_PER_CTA + threadIdx.x;
    const int bx = tid & 63;          // block col (0..63)
    const int by = (tid >> 6) & 63;   // block row (0..63)
    const int bc = tid >> 12;         // image-plane (0..95)

    // base fits in 2^27 elements -> 32-bit offset arithmetic, immediates per row
    const int base = (bc << 18) + (by << 12) + (bx << 3);
    const float* __restrict__ p = in + base;
    float* __restrict__ q = out + base;

    float x[8][8];

    // ---- load 8x8 block (2x LDG.128.CS per row; warp covers contiguous 1KB) ----
#pragma unroll
    for (int r = 0; r < 8; r++) {
        *reinterpret_cast<float4*>(&x[r][0]) =
            __ldcs(reinterpret_cast<const float4*>(p + (r << 9)));
        *reinterpret_cast<float4*>(&x[r][4]) =
            __ldcs(reinterpret_cast<const float4*>(p + (r << 9) + 4));
    }

    // ---- forward DCT: rows (X D^T), then cols ----
#pragma unroll
    for (int i = 0; i < 8; i++) {
        fwd8(x[i][0], x[i][1], x[i][2], x[i][3], x[i][4], x[i][5], x[i][6], x[i][7],
             x[i][0], x[i][1], x[i][2], x[i][3], x[i][4], x[i][5], x[i][6], x[i][7]);
    }
#pragma unroll
    for (int j = 0; j < 8; j++) {
        fwd8(x[0][j], x[1][j], x[2][j], x[3][j], x[4][j], x[5][j], x[6][j], x[7][j],
             x[0][j], x[1][j], x[2][j], x[3][j], x[4][j], x[5][j], x[6][j], x[7][j]);
    }

    // ---- quantize (round half-to-even) + dequantize, in place ----
#pragma unroll
    for (int i = 0; i < 8; i++) {
#pragma unroll
        for (int j = 0; j < 8; j++) {
            x[i][j] = round_even(x[i][j] * (1.0f / Qm[i][j])) * Qm[i][j];
        }
    }

    // ---- inverse DCT: rows, then cols ----
#pragma unroll
    for (int i = 0; i < 8; i++) {
        inv8(x[i][0], x[i][1], x[i][2], x[i][3], x[i][4], x[i][5], x[i][6], x[i][7],
             x[i][0], x[i][1], x[i][2], x[i][3], x[i][4], x[i][5], x[i][6], x[i][7]);
    }
#pragma unroll
    for (int j = 0; j < 8; j++) {
        inv8(x[0][j], x[1][j], x[2][j], x[3][j], x[4][j], x[5][j], x[6][j], x[7][j],
             x[0][j], x[1][j], x[2][j], x[3][j], x[4][j], x[5][j], x[6][j], x[7][j]);
    }

    // ---- store 8x8 block (STG.128.CS) ----
#pragma unroll
    for (int r = 0; r < 8; r++) {
        __stcs(reinterpret_cast<float4*>(q + (r << 9)),
               *reinterpret_cast<const float4*>(&x[r][0]));
        __stcs(reinterpret_cast<float4*>(q + (r << 9) + 4),
               *reinterpret_cast<const float4*>(&x[r][4]));
    }
}

extern "C" void kernel_launch(void* const* d_in, const int* in_sizes, int n_in,
                              void* d_out, int out_size) {
    (void)in_sizes; (void)n_in; (void)out_size;
    const float* img = (const float*)d_in[0];
    float* out = (float*)d_out;
    const int grid = NUM_BLOCKS_TOTAL / THREADS_PER_CTA;  // 1536
    diffjpeg_kernel<<<grid, THREADS_PER_CTA>>>(img, out);
}